// round 5
// baseline (speedup 1.0000x reference)
#include <cuda_runtime.h>
#include <cuda_bf16.h>

#define N_NODES 100000
#define N_EDGES 1600000
#define D 32
#define ED 8
#define FULL 0xffffffffu

// Ping-pong node features + per-node aggregate (written once, no atomics).
__device__ float g_buf0[N_NODES * D];
__device__ float g_buf1[N_NODES * D];
__device__ float g_agg[N_NODES * D];
// CSR build
__device__ int   g_count[N_NODES];
__device__ int   g_rowptr[N_NODES + 1];
__device__ int   g_cursor[N_NODES];
__device__ int   g_src_sorted[N_EDGES];
__device__ float g_ea_sorted[N_EDGES * ED];   // edge_attr permuted to dst order

// ---------------------------------------------------------------------------
// 1) zero in-degree counters
// ---------------------------------------------------------------------------
__global__ void zero_counts_kernel() {
    for (int i = blockIdx.x * blockDim.x + threadIdx.x; i < N_NODES;
         i += gridDim.x * blockDim.x)
        g_count[i] = 0;
}

// ---------------------------------------------------------------------------
// 2) histogram of dst
// ---------------------------------------------------------------------------
__global__ void hist_kernel(const int* __restrict__ dst) {
    for (int e = blockIdx.x * blockDim.x + threadIdx.x; e < N_EDGES;
         e += gridDim.x * blockDim.x)
        atomicAdd(&g_count[dst[e]], 1);
}

// ---------------------------------------------------------------------------
// 3) exclusive scan -> rowptr + cursors (single block, chunked, verified R3)
// ---------------------------------------------------------------------------
__global__ __launch_bounds__(1024) void scan_kernel() {
    __shared__ int warp_tot[32];
    __shared__ int chunk_tot;
    const int tid  = threadIdx.x;
    const int lane = tid & 31;
    const int w    = tid >> 5;
    int carry = 0;

    for (int base = 0; base < N_NODES; base += 1024) {
        const int i = base + tid;
        int v = (i < N_NODES) ? g_count[i] : 0;

        int incl = v;
#pragma unroll
        for (int off = 1; off < 32; off <<= 1) {
            int t = __shfl_up_sync(FULL, incl, off);
            if (lane >= off) incl += t;
        }
        if (lane == 31) warp_tot[w] = incl;
        __syncthreads();

        if (w == 0) {
            int t  = warp_tot[lane];
            int ti = t;
#pragma unroll
            for (int off = 1; off < 32; off <<= 1) {
                int u = __shfl_up_sync(FULL, ti, off);
                if (lane >= off) ti += u;
            }
            warp_tot[lane] = ti - t;
            if (lane == 31) chunk_tot = ti;
        }
        __syncthreads();

        const int excl = incl - v + warp_tot[w] + carry;
        if (i < N_NODES) {
            g_rowptr[i] = excl;
            g_cursor[i] = excl;
        }
        carry += chunk_tot;
        __syncthreads();
    }
    if (tid == 0) g_rowptr[N_NODES] = carry;
}

// ---------------------------------------------------------------------------
// 4) scatter edges into dst-sorted order, fusing the edge_attr permute.
// ---------------------------------------------------------------------------
__global__ void scatter_kernel(const int* __restrict__ src,
                               const int* __restrict__ dst,
                               const float* __restrict__ ea) {
    for (int e = blockIdx.x * blockDim.x + threadIdx.x; e < N_EDGES;
         e += gridDim.x * blockDim.x) {
        const int d   = dst[e];
        const int pos = atomicAdd(&g_cursor[d], 1);
        g_src_sorted[pos] = src[e];
        const float4* s = reinterpret_cast<const float4*>(ea + (size_t)e * ED);
        float4 a0 = s[0], a1 = s[1];
        float4* o = reinterpret_cast<float4*>(g_ea_sorted + (size_t)pos * ED);
        o[0] = a0;
        o[1] = a1;
    }
}

// ---------------------------------------------------------------------------
// Per-layer gather kernel: warp per node, 4 edges per iteration.
//   lane layout: g = lane>>3 edge-in-quad, c = lane&7 column quad.
// Register-accumulated segment sum; one STG.128 row store per node. NO atomics.
// ---------------------------------------------------------------------------
__global__ __launch_bounds__(256) void gather_kernel(
    const float* __restrict__ x_ext, int x_sel,
    const float* __restrict__ We,   // layer slice: [8, 32]
    const float* __restrict__ be)   // layer slice: [32]
{
    const float* x = (x_sel == 0) ? x_ext : (x_sel == 1 ? g_buf0 : g_buf1);

    const int lane = threadIdx.x & 31;
    const int c    = lane & 7;    // column quad (cols 4c..4c+3)
    const int g    = lane >> 3;   // edge within quad
    const int q    = lane & 3;    // src-load slot
    const int wid  = (blockIdx.x * blockDim.x + threadIdx.x) >> 5;
    const int nw   = (gridDim.x * blockDim.x) >> 5;

    float4 wv[ED];
#pragma unroll
    for (int k = 0; k < ED; k++)
        wv[k] = *reinterpret_cast<const float4*>(We + k * D + c * 4);
    const float4 bias = *reinterpret_cast<const float4*>(be + c * 4);

    for (int node = wid; node < N_NODES; node += nw) {
        const int beg = __ldg(&g_rowptr[node]);
        const int end = __ldg(&g_rowptr[node + 1]);

        float4 acc = make_float4(0.f, 0.f, 0.f, 0.f);
        for (int p = beg; p < end; p += 4) {
            // lanes 0..3 load up to 4 consecutive src ids (coalesced)
            const int pe = p + q;
            const int sv = (pe < end) ? __ldg(g_src_sorted + pe) : 0;
            const int s  = __shfl_sync(FULL, sv, g);
            // lane reads attr (lane&7) of edge p+(lane>>3) (coalesced 128B)
            const float av = (p + (lane >> 3) < end)
                                 ? __ldg(g_ea_sorted + (size_t)p * ED + lane)
                                 : 0.0f;
            const bool valid = (p + g) < end;

            float4 e4 = bias;
#pragma unroll
            for (int k = 0; k < ED; k++) {
                const float f = __shfl_sync(FULL, av, (g << 3) | k);
                e4.x = fmaf(f, wv[k].x, e4.x);
                e4.y = fmaf(f, wv[k].y, e4.y);
                e4.z = fmaf(f, wv[k].z, e4.z);
                e4.w = fmaf(f, wv[k].w, e4.w);
            }
            const float4 xv =
                __ldg(reinterpret_cast<const float4*>(x + (size_t)s * D + c * 4));
            if (valid) {
                acc.x += fmaxf(xv.x + e4.x, 0.0f);
                acc.y += fmaxf(xv.y + e4.y, 0.0f);
                acc.z += fmaxf(xv.z + e4.z, 0.0f);
                acc.w += fmaxf(xv.w + e4.w, 0.0f);
            }
        }

        // reduce the 4 edge-groups (lanes xor 8, 16)
#pragma unroll
        for (int off = 8; off <= 16; off <<= 1) {
            acc.x += __shfl_xor_sync(FULL, acc.x, off);
            acc.y += __shfl_xor_sync(FULL, acc.y, off);
            acc.z += __shfl_xor_sync(FULL, acc.z, off);
            acc.w += __shfl_xor_sync(FULL, acc.w, off);
        }
        if (g == 0) {   // lanes 0..7: one coalesced 128B row store
            *reinterpret_cast<float4*>(g_agg + (size_t)node * D + c * 4) = acc;
        }
    }
}

// ---------------------------------------------------------------------------
// Node kernel: one warp per node (unchanged, measured fast).
// ---------------------------------------------------------------------------
__global__ __launch_bounds__(256) void node_kernel(
    const float* __restrict__ x_ext, int x_sel,
    float* __restrict__ out_ext, int out_sel,
    const float* __restrict__ W,    // [32, 32]
    const float* __restrict__ b)    // [32]
{
    const float* x  = (x_sel == 0) ? x_ext : (x_sel == 1 ? g_buf0 : g_buf1);
    float* out = (out_sel == 0) ? out_ext : (out_sel == 1 ? g_buf0 : g_buf1);

    const int lane = threadIdx.x & 31;
    const int wid  = (blockIdx.x * blockDim.x + threadIdx.x) >> 5;
    const int nw   = (gridDim.x * blockDim.x) >> 5;

    float w[D];
#pragma unroll
    for (int k = 0; k < D; k++) w[k] = W[k * D + lane];
    const float bias = b[lane];

    for (int node = wid; node < N_NODES; node += nw) {
        const float h = x[node * D + lane] + g_agg[node * D + lane];
        float acc = bias;
#pragma unroll
        for (int k = 0; k < D; k++)
            acc = fmaf(__shfl_sync(FULL, h, k), w[k], acc);
        out[node * D + lane] = fmaxf(acc, 0.01f * acc);  // leaky_relu 0.01
    }
}

// ---------------------------------------------------------------------------
extern "C" void kernel_launch(void* const* d_in, const int* in_sizes, int n_in,
                              void* d_out, int out_size)
{
    const float* x   = (const float*)d_in[0];
    const float* ea  = (const float*)d_in[1];
    const float* W   = (const float*)d_in[2];
    const float* b   = (const float*)d_in[3];
    const float* We  = (const float*)d_in[4];
    const float* be  = (const float*)d_in[5];
    const int*   ei  = (const int*)d_in[6];
    float* out = (float*)d_out;

    const int* src = ei;
    const int* dst = ei + N_EDGES;

    // CSR build, once per call (amortized over 3 layers)
    zero_counts_kernel<<<196, 512>>>();
    hist_kernel<<<1184, 256>>>(dst);
    scan_kernel<<<1, 1024>>>();
    scatter_kernel<<<1184, 256>>>(src, dst, ea);

    const int x_sels[3]   = {0, 1, 2};
    const int out_sels[3] = {1, 2, 0};
    for (int l = 0; l < 3; l++) {
        gather_kernel<<<1184, 256>>>(x, x_sels[l],
                                     We + l * ED * D, be + l * D);
        node_kernel<<<592, 256>>>(x, x_sels[l], out, out_sels[l],
                                  W + l * D * D, b + l * D);
    }
}

// round 6
// speedup vs baseline: 1.5769x; 1.5769x over previous
#include <cuda_runtime.h>
#include <cuda_bf16.h>

#define N_NODES 100000
#define N_EDGES 1600000
#define D 32
#define ED 8
#define FULL 0xffffffffu

// Ping-pong node features + aggregation buffer.
__device__ float g_buf0[N_NODES * D];
__device__ float g_buf1[N_NODES * D];
__device__ float g_agg[N_NODES * D];

// ---------------------------------------------------------------------------
// Zero the aggregation buffer (float4 grid-stride). ~6us measured.
// ---------------------------------------------------------------------------
__global__ void zero_agg_kernel() {
    const int n4 = N_NODES * D / 4;
    float4* p = reinterpret_cast<float4*>(g_agg);
    float4 z = make_float4(0.f, 0.f, 0.f, 0.f);
    for (int i = blockIdx.x * blockDim.x + threadIdx.x; i < n4;
         i += gridDim.x * blockDim.x) {
        p[i] = z;
    }
}

// ---------------------------------------------------------------------------
// Edge kernel: 8 edges per warp per iteration (2 independent 4-edge groups).
//   lane layout: g = lane>>3 edge-in-quad, c = lane&7 column quad (4c..4c+3).
// We lives in SMEM (broadcast LDS per k) to cut register pressure -> higher
// occupancy. Edge attrs via direct LDG.128 (broadcast sectors), no SHFL.
// ---------------------------------------------------------------------------
__global__ __launch_bounds__(256) void edge_kernel(
    const float* __restrict__ x_ext, int x_sel,
    const float* __restrict__ edge_attr,
    const float* __restrict__ We,   // layer slice: [8, 32]
    const float* __restrict__ be,   // layer slice: [32]
    const int*   __restrict__ src,
    const int*   __restrict__ dst)
{
    const float* x = (x_sel == 0) ? x_ext : (x_sel == 1 ? g_buf0 : g_buf1);

    // s_we[k*8 + c] = We[k][4c..4c+3]; s_bias[c] = be[4c..4c+3]
    __shared__ float4 s_we[ED * 8];
    __shared__ float4 s_bias[8];
    {
        const int t = threadIdx.x;
        if (t < 64) {
            const int k = t >> 3, cc = t & 7;
            s_we[t] = *reinterpret_cast<const float4*>(We + k * D + cc * 4);
        } else if (t < 72) {
            s_bias[t - 64] = *reinterpret_cast<const float4*>(be + (t - 64) * 4);
        }
    }
    __syncthreads();

    const int lane = threadIdx.x & 31;
    const int c    = lane & 7;    // column quad index
    const int g    = lane >> 3;   // edge within the 4-edge group
    const int wid  = (blockIdx.x * blockDim.x + threadIdx.x) >> 5;
    const int nw   = (gridDim.x * blockDim.x) >> 5;

    const float4 bias = s_bias[c];

    // N_EDGES % 8 == 0, so every iteration is a full 8-edge tile.
    for (int e8 = wid * 8; e8 < N_EDGES; e8 += nw * 8) {
        // Front-load all independent memory ops.
        const int s0 = __ldg(src + e8 + g);
        const int d0 = __ldg(dst + e8 + g);
        const int s1 = __ldg(src + e8 + 4 + g);
        const int d1 = __ldg(dst + e8 + 4 + g);

        // All 8 attrs of this lane's edge, as two float4s (broadcast within
        // each 8-lane column group; 4 distinct 16B sectors per warp per load).
        const float4 al0 = __ldg(reinterpret_cast<const float4*>(
            edge_attr + (size_t)(e8 + g) * ED));
        const float4 ah0 = __ldg(reinterpret_cast<const float4*>(
            edge_attr + (size_t)(e8 + g) * ED + 4));
        const float4 al1 = __ldg(reinterpret_cast<const float4*>(
            edge_attr + (size_t)(e8 + 4 + g) * ED));
        const float4 ah1 = __ldg(reinterpret_cast<const float4*>(
            edge_attr + (size_t)(e8 + 4 + g) * ED + 4));

        const float4 xv0 =
            __ldg(reinterpret_cast<const float4*>(x + (size_t)s0 * D + c * 4));
        const float4 xv1 =
            __ldg(reinterpret_cast<const float4*>(x + (size_t)s1 * D + c * 4));

        float a0arr[ED] = {al0.x, al0.y, al0.z, al0.w, ah0.x, ah0.y, ah0.z, ah0.w};
        float a1arr[ED] = {al1.x, al1.y, al1.z, al1.w, ah1.x, ah1.y, ah1.z, ah1.w};

        float4 a0 = bias, a1 = bias;
#pragma unroll
        for (int k = 0; k < ED; k++) {
            const float4 wk = s_we[k * 8 + c];   // broadcast LDS.128
            const float f0 = a0arr[k];
            const float f1 = a1arr[k];
            a0.x = fmaf(f0, wk.x, a0.x);
            a0.y = fmaf(f0, wk.y, a0.y);
            a0.z = fmaf(f0, wk.z, a0.z);
            a0.w = fmaf(f0, wk.w, a0.w);
            a1.x = fmaf(f1, wk.x, a1.x);
            a1.y = fmaf(f1, wk.y, a1.y);
            a1.z = fmaf(f1, wk.z, a1.z);
            a1.w = fmaf(f1, wk.w, a1.w);
        }

        float4 m0, m1;
        m0.x = fmaxf(xv0.x + a0.x, 0.0f);
        m0.y = fmaxf(xv0.y + a0.y, 0.0f);
        m0.z = fmaxf(xv0.z + a0.z, 0.0f);
        m0.w = fmaxf(xv0.w + a0.w, 0.0f);
        m1.x = fmaxf(xv1.x + a1.x, 0.0f);
        m1.y = fmaxf(xv1.y + a1.y, 0.0f);
        m1.z = fmaxf(xv1.z + a1.z, 0.0f);
        m1.w = fmaxf(xv1.w + a1.w, 0.0f);

        float* p0 = g_agg + (size_t)d0 * D + c * 4;
        float* p1 = g_agg + (size_t)d1 * D + c * 4;
        asm volatile("red.global.add.v4.f32 [%0], {%1,%2,%3,%4};"
                     :: "l"(p0), "f"(m0.x), "f"(m0.y), "f"(m0.z), "f"(m0.w)
                     : "memory");
        asm volatile("red.global.add.v4.f32 [%0], {%1,%2,%3,%4};"
                     :: "l"(p1), "f"(m1.x), "f"(m1.y), "f"(m1.z), "f"(m1.w)
                     : "memory");
    }
}

// ---------------------------------------------------------------------------
// Node kernel: one warp per node (measured ~12us/layer).
// ---------------------------------------------------------------------------
__global__ __launch_bounds__(256) void node_kernel(
    const float* __restrict__ x_ext, int x_sel,
    float* __restrict__ out_ext, int out_sel,
    const float* __restrict__ W,    // [32, 32]
    const float* __restrict__ b)    // [32]
{
    const float* x  = (x_sel == 0) ? x_ext : (x_sel == 1 ? g_buf0 : g_buf1);
    float* out = (out_sel == 0) ? out_ext : (out_sel == 1 ? g_buf0 : g_buf1);

    const int lane = threadIdx.x & 31;
    const int wid  = (blockIdx.x * blockDim.x + threadIdx.x) >> 5;
    const int nw   = (gridDim.x * blockDim.x) >> 5;

    float w[D];
#pragma unroll
    for (int k = 0; k < D; k++) w[k] = W[k * D + lane];
    const float bias = b[lane];

    for (int node = wid; node < N_NODES; node += nw) {
        const float h = x[node * D + lane] + g_agg[node * D + lane];
        float acc = bias;
#pragma unroll
        for (int k = 0; k < D; k++)
            acc = fmaf(__shfl_sync(FULL, h, k), w[k], acc);
        out[node * D + lane] = fmaxf(acc, 0.01f * acc);  // leaky_relu 0.01
    }
}

// ---------------------------------------------------------------------------
// 3 layers of { zero agg; edge scatter; node transform }.
// Ping-pong: ext -> g_buf0 -> g_buf1 -> d_out.
// ---------------------------------------------------------------------------
extern "C" void kernel_launch(void* const* d_in, const int* in_sizes, int n_in,
                              void* d_out, int out_size)
{
    const float* x   = (const float*)d_in[0];   // [N, 32]
    const float* ea  = (const float*)d_in[1];   // [E, 8]
    const float* W   = (const float*)d_in[2];   // [3, 32, 32]
    const float* b   = (const float*)d_in[3];   // [3, 32]
    const float* We  = (const float*)d_in[4];   // [3, 8, 32]
    const float* be  = (const float*)d_in[5];   // [3, 32]
    const int*   ei  = (const int*)d_in[6];     // [2, E] int32
    float* out = (float*)d_out;

    const int* src = ei;
    const int* dst = ei + N_EDGES;

    const int x_sels[3]   = {0, 1, 2};
    const int out_sels[3] = {1, 2, 0};

    for (int l = 0; l < 3; l++) {
        zero_agg_kernel<<<1184, 256>>>();
        edge_kernel<<<1184, 256>>>(
            x, x_sels[l], ea, We + l * ED * D, be + l * D, src, dst);
        node_kernel<<<592, 256>>>(
            x, x_sels[l], out, out_sels[l], W + l * D * D, b + l * D);
    }
}

// round 7
// speedup vs baseline: 1.7008x; 1.0785x over previous
#include <cuda_runtime.h>
#include <cuda_bf16.h>

#define N_NODES 100000
#define N_EDGES 1600000
#define D 32
#define ED 8
#define FULL 0xffffffffu

// Ping-pong node features + per-layer aggregation buffers (zeroed once).
__device__ float g_buf0[N_NODES * D];
__device__ float g_buf1[N_NODES * D];
__device__ float g_agg[3][N_NODES * D];

// ---------------------------------------------------------------------------
// Zero ALL three aggregation buffers in one pass (runs once per call).
// ---------------------------------------------------------------------------
__global__ void zero_all_kernel() {
    const int n4 = 3 * N_NODES * D / 4;
    float4* p = reinterpret_cast<float4*>(&g_agg[0][0]);
    float4 z = make_float4(0.f, 0.f, 0.f, 0.f);
    for (int i = blockIdx.x * blockDim.x + threadIdx.x; i < n4;
         i += gridDim.x * blockDim.x) {
        p[i] = z;
    }
}

// ---------------------------------------------------------------------------
// Edge kernel (R4 formulation + index-prefetch software pipeline):
// 8 edges per warp-iteration, 2 independent 4-edge groups.
//   lane layout: g = lane>>3 edge-in-quad, c = lane&7 column quad (4c..4c+3).
// The src/dst indices of the NEXT tile are prefetched during the current
// tile's compute, so each tile's x-gather never waits on its index load.
// ---------------------------------------------------------------------------
__global__ __launch_bounds__(128) void edge_kernel(
    const float* __restrict__ x_ext, int x_sel, int layer,
    const float* __restrict__ edge_attr,
    const float* __restrict__ We,   // layer slice: [8, 32]
    const float* __restrict__ be,   // layer slice: [32]
    const int*   __restrict__ src,
    const int*   __restrict__ dst)
{
    const float* x = (x_sel == 0) ? x_ext : (x_sel == 1 ? g_buf0 : g_buf1);
    float* agg = &g_agg[layer][0];

    const int lane = threadIdx.x & 31;
    const int c    = lane & 7;    // column quad index
    const int g    = lane >> 3;   // edge within the 4-edge group
    const int wid  = (blockIdx.x * blockDim.x + threadIdx.x) >> 5;
    const int nw   = (gridDim.x * blockDim.x) >> 5;

    float4 wv[ED];
#pragma unroll
    for (int k = 0; k < ED; k++)
        wv[k] = *reinterpret_cast<const float4*>(We + k * D + c * 4);
    const float4 bias = *reinterpret_cast<const float4*>(be + c * 4);

    int e8 = wid * 8;
    if (e8 >= N_EDGES) return;

    // Prologue: load first tile's indices. (N_EDGES % 8 == 0, tiles full.)
    int s0 = __ldg(src + e8 + g);
    int d0 = __ldg(dst + e8 + g);
    int s1 = __ldg(src + e8 + 4 + g);
    int d1 = __ldg(dst + e8 + 4 + g);

    const int stride = nw * 8;
    for (; e8 < N_EDGES; e8 += stride) {
        // Issue gathers immediately — indices are already resident.
        const float4 xv0 =
            __ldg(reinterpret_cast<const float4*>(x + (size_t)s0 * D + c * 4));
        const float4 xv1 =
            __ldg(reinterpret_cast<const float4*>(x + (size_t)s1 * D + c * 4));
        // Attr loads (chain-free, addressed by e8).
        const float av0 = __ldg(edge_attr + (size_t)e8 * ED + lane);
        const float av1 = __ldg(edge_attr + (size_t)(e8 + 4) * ED + lane);

        // Prefetch next tile's indices (clamped; discarded on last iter).
        const int n8 = e8 + stride;
        const int n8c = (n8 < N_EDGES) ? n8 : 0;
        const int ns0 = __ldg(src + n8c + g);
        const int nd0 = __ldg(dst + n8c + g);
        const int ns1 = __ldg(src + n8c + 4 + g);
        const int nd1 = __ldg(dst + n8c + 4 + g);

        float4 a0 = bias, a1 = bias;
#pragma unroll
        for (int k = 0; k < ED; k++) {
            const float f0 = __shfl_sync(FULL, av0, (g << 3) | k);
            const float f1 = __shfl_sync(FULL, av1, (g << 3) | k);
            a0.x = fmaf(f0, wv[k].x, a0.x);
            a0.y = fmaf(f0, wv[k].y, a0.y);
            a0.z = fmaf(f0, wv[k].z, a0.z);
            a0.w = fmaf(f0, wv[k].w, a0.w);
            a1.x = fmaf(f1, wv[k].x, a1.x);
            a1.y = fmaf(f1, wv[k].y, a1.y);
            a1.z = fmaf(f1, wv[k].z, a1.z);
            a1.w = fmaf(f1, wv[k].w, a1.w);
        }

        float4 m0, m1;
        m0.x = fmaxf(xv0.x + a0.x, 0.0f);
        m0.y = fmaxf(xv0.y + a0.y, 0.0f);
        m0.z = fmaxf(xv0.z + a0.z, 0.0f);
        m0.w = fmaxf(xv0.w + a0.w, 0.0f);
        m1.x = fmaxf(xv1.x + a1.x, 0.0f);
        m1.y = fmaxf(xv1.y + a1.y, 0.0f);
        m1.z = fmaxf(xv1.z + a1.z, 0.0f);
        m1.w = fmaxf(xv1.w + a1.w, 0.0f);

        float* p0 = agg + (size_t)d0 * D + c * 4;
        float* p1 = agg + (size_t)d1 * D + c * 4;
        asm volatile("red.global.add.v4.f32 [%0], {%1,%2,%3,%4};"
                     :: "l"(p0), "f"(m0.x), "f"(m0.y), "f"(m0.z), "f"(m0.w)
                     : "memory");
        asm volatile("red.global.add.v4.f32 [%0], {%1,%2,%3,%4};"
                     :: "l"(p1), "f"(m1.x), "f"(m1.y), "f"(m1.z), "f"(m1.w)
                     : "memory");

        // Rotate pipeline registers.
        s0 = ns0; d0 = nd0; s1 = ns1; d1 = nd1;
    }
}

// ---------------------------------------------------------------------------
// Node kernel: one warp per node (measured ~12us/layer, unchanged).
// ---------------------------------------------------------------------------
__global__ __launch_bounds__(256) void node_kernel(
    const float* __restrict__ x_ext, int x_sel, int layer,
    float* __restrict__ out_ext, int out_sel,
    const float* __restrict__ W,    // [32, 32]
    const float* __restrict__ b)    // [32]
{
    const float* x  = (x_sel == 0) ? x_ext : (x_sel == 1 ? g_buf0 : g_buf1);
    float* out = (out_sel == 0) ? out_ext : (out_sel == 1 ? g_buf0 : g_buf1);
    const float* agg = &g_agg[layer][0];

    const int lane = threadIdx.x & 31;
    const int wid  = (blockIdx.x * blockDim.x + threadIdx.x) >> 5;
    const int nw   = (gridDim.x * blockDim.x) >> 5;

    float w[D];
#pragma unroll
    for (int k = 0; k < D; k++) w[k] = W[k * D + lane];
    const float bias = b[lane];

    for (int node = wid; node < N_NODES; node += nw) {
        const float h = x[node * D + lane] + agg[node * D + lane];
        float acc = bias;
#pragma unroll
        for (int k = 0; k < D; k++)
            acc = fmaf(__shfl_sync(FULL, h, k), w[k], acc);
        out[node * D + lane] = fmaxf(acc, 0.01f * acc);  // leaky_relu 0.01
    }
}

// ---------------------------------------------------------------------------
// zero all aggs once; then 3 layers of { edge scatter; node transform }.
// Ping-pong: ext -> g_buf0 -> g_buf1 -> d_out.
// ---------------------------------------------------------------------------
extern "C" void kernel_launch(void* const* d_in, const int* in_sizes, int n_in,
                              void* d_out, int out_size)
{
    const float* x   = (const float*)d_in[0];   // [N, 32]
    const float* ea  = (const float*)d_in[1];   // [E, 8]
    const float* W   = (const float*)d_in[2];   // [3, 32, 32]
    const float* b   = (const float*)d_in[3];   // [3, 32]
    const float* We  = (const float*)d_in[4];   // [3, 8, 32]
    const float* be  = (const float*)d_in[5];   // [3, 32]
    const int*   ei  = (const int*)d_in[6];     // [2, E] int32
    float* out = (float*)d_out;

    const int* src = ei;
    const int* dst = ei + N_EDGES;

    const int x_sels[3]   = {0, 1, 2};
    const int out_sels[3] = {1, 2, 0};

    zero_all_kernel<<<1184, 256>>>();
    for (int l = 0; l < 3; l++) {
        edge_kernel<<<2368, 128>>>(
            x, x_sels[l], l, ea, We + l * ED * D, be + l * D, src, dst);
        node_kernel<<<592, 256>>>(
            x, x_sels[l], l, out, out_sels[l], W + l * D * D, b + l * D);
    }
}

// round 8
// speedup vs baseline: 1.9265x; 1.1327x over previous
#include <cuda_runtime.h>
#include <cuda_bf16.h>

#define N_NODES 100000
#define N_EDGES 1600000
#define D 32
#define ED 8
#define FULL 0xffffffffu

// Ping-pong node features + per-layer aggregation buffers (zeroed once).
__device__ float g_buf0[N_NODES * D];
__device__ float g_buf1[N_NODES * D];
__device__ float g_agg[3][N_NODES * D];

// ---------------------------------------------------------------------------
// Zero ALL three aggregation buffers in one pass (runs once per call).
// ---------------------------------------------------------------------------
__global__ void zero_all_kernel() {
    const int n4 = 3 * N_NODES * D / 4;
    float4* p = reinterpret_cast<float4*>(&g_agg[0][0]);
    float4 z = make_float4(0.f, 0.f, 0.f, 0.f);
    for (int i = blockIdx.x * blockDim.x + threadIdx.x; i < n4;
         i += gridDim.x * blockDim.x) {
        p[i] = z;
    }
}

// ---------------------------------------------------------------------------
// Edge kernel: 16 edges per warp-iteration (4 independent 4-edge groups)
// + next-tile index prefetch. lane layout: g = lane>>3 edge-in-quad,
// c = lane&7 column quad (cols 4c..4c+3).
// Per tile: 4 independent x-gather LDG.128 + 4 RED.128 in flight (MLP=4).
// ---------------------------------------------------------------------------
__global__ __launch_bounds__(128) void edge_kernel(
    const float* __restrict__ x_ext, int x_sel, int layer,
    const float* __restrict__ edge_attr,
    const float* __restrict__ We,   // layer slice: [8, 32]
    const float* __restrict__ be,   // layer slice: [32]
    const int*   __restrict__ src,
    const int*   __restrict__ dst)
{
    const float* x = (x_sel == 0) ? x_ext : (x_sel == 1 ? g_buf0 : g_buf1);
    float* agg = &g_agg[layer][0];

    const int lane = threadIdx.x & 31;
    const int c    = lane & 7;
    const int g    = lane >> 3;
    const int wid  = (blockIdx.x * blockDim.x + threadIdx.x) >> 5;
    const int nw   = (gridDim.x * blockDim.x) >> 5;

    float4 wv[ED];
#pragma unroll
    for (int k = 0; k < ED; k++)
        wv[k] = *reinterpret_cast<const float4*>(We + k * D + c * 4);
    const float4 bias = *reinterpret_cast<const float4*>(be + c * 4);

    int e16 = wid * 16;
    if (e16 >= N_EDGES) return;

    // Prologue: first tile's indices. N_EDGES % 16 == 0 -> all tiles full.
    int s[4], d[4];
#pragma unroll
    for (int u = 0; u < 4; u++) {
        s[u] = __ldg(src + e16 + u * 4 + g);
        d[u] = __ldg(dst + e16 + u * 4 + g);
    }

    const int stride = nw * 16;
    for (; e16 < N_EDGES; e16 += stride) {
        // 4 independent gathers issue immediately (indices resident).
        float4 xv[4];
#pragma unroll
        for (int u = 0; u < 4; u++)
            xv[u] = __ldg(reinterpret_cast<const float4*>(
                x + (size_t)s[u] * D + c * 4));

        // Attr loads (chain-free).
        float av[4];
#pragma unroll
        for (int u = 0; u < 4; u++)
            av[u] = __ldg(edge_attr + (size_t)(e16 + u * 4) * ED + lane);

        // Prefetch next tile's indices (clamped on last iteration).
        const int n16 = e16 + stride;
        const int nc  = (n16 < N_EDGES) ? n16 : 0;
        int ns[4], nd[4];
#pragma unroll
        for (int u = 0; u < 4; u++) {
            ns[u] = __ldg(src + nc + u * 4 + g);
            nd[u] = __ldg(dst + nc + u * 4 + g);
        }

        float4 a[4];
#pragma unroll
        for (int u = 0; u < 4; u++) a[u] = bias;
#pragma unroll
        for (int k = 0; k < ED; k++) {
            const float4 wk = wv[k];
#pragma unroll
            for (int u = 0; u < 4; u++) {
                const float f = __shfl_sync(FULL, av[u], (g << 3) | k);
                a[u].x = fmaf(f, wk.x, a[u].x);
                a[u].y = fmaf(f, wk.y, a[u].y);
                a[u].z = fmaf(f, wk.z, a[u].z);
                a[u].w = fmaf(f, wk.w, a[u].w);
            }
        }

#pragma unroll
        for (int u = 0; u < 4; u++) {
            float4 m;
            m.x = fmaxf(xv[u].x + a[u].x, 0.0f);
            m.y = fmaxf(xv[u].y + a[u].y, 0.0f);
            m.z = fmaxf(xv[u].z + a[u].z, 0.0f);
            m.w = fmaxf(xv[u].w + a[u].w, 0.0f);
            float* p = agg + (size_t)d[u] * D + c * 4;
            asm volatile("red.global.add.v4.f32 [%0], {%1,%2,%3,%4};"
                         :: "l"(p), "f"(m.x), "f"(m.y), "f"(m.z), "f"(m.w)
                         : "memory");
        }

#pragma unroll
        for (int u = 0; u < 4; u++) { s[u] = ns[u]; d[u] = nd[u]; }
    }
}

// ---------------------------------------------------------------------------
// Node kernel: one warp per node (measured ~12us/layer, unchanged).
// ---------------------------------------------------------------------------
__global__ __launch_bounds__(256) void node_kernel(
    const float* __restrict__ x_ext, int x_sel, int layer,
    float* __restrict__ out_ext, int out_sel,
    const float* __restrict__ W,    // [32, 32]
    const float* __restrict__ b)    // [32]
{
    const float* x  = (x_sel == 0) ? x_ext : (x_sel == 1 ? g_buf0 : g_buf1);
    float* out = (out_sel == 0) ? out_ext : (out_sel == 1 ? g_buf0 : g_buf1);
    const float* agg = &g_agg[layer][0];

    const int lane = threadIdx.x & 31;
    const int wid  = (blockIdx.x * blockDim.x + threadIdx.x) >> 5;
    const int nw   = (gridDim.x * blockDim.x) >> 5;

    float w[D];
#pragma unroll
    for (int k = 0; k < D; k++) w[k] = W[k * D + lane];
    const float bias = b[lane];

    for (int node = wid; node < N_NODES; node += nw) {
        const float h = x[node * D + lane] + agg[node * D + lane];
        float acc = bias;
#pragma unroll
        for (int k = 0; k < D; k++)
            acc = fmaf(__shfl_sync(FULL, h, k), w[k], acc);
        out[node * D + lane] = fmaxf(acc, 0.01f * acc);  // leaky_relu 0.01
    }
}

// ---------------------------------------------------------------------------
extern "C" void kernel_launch(void* const* d_in, const int* in_sizes, int n_in,
                              void* d_out, int out_size)
{
    const float* x   = (const float*)d_in[0];   // [N, 32]
    const float* ea  = (const float*)d_in[1];   // [E, 8]
    const float* W   = (const float*)d_in[2];   // [3, 32, 32]
    const float* b   = (const float*)d_in[3];   // [3, 32]
    const float* We  = (const float*)d_in[4];   // [3, 8, 32]
    const float* be  = (const float*)d_in[5];   // [3, 32]
    const int*   ei  = (const int*)d_in[6];     // [2, E] int32
    float* out = (float*)d_out;

    const int* src = ei;
    const int* dst = ei + N_EDGES;

    const int x_sels[3]   = {0, 1, 2};
    const int out_sels[3] = {1, 2, 0};

    zero_all_kernel<<<1184, 256>>>();
    for (int l = 0; l < 3; l++) {
        edge_kernel<<<2368, 128>>>(
            x, x_sels[l], l, ea, We + l * ED * D, be + l * D, src, dst);
        node_kernel<<<592, 256>>>(
            x, x_sels[l], l, out, out_sels[l], W + l * D * D, b + l * D);
    }
}